// round 1
// baseline (speedup 1.0000x reference)
#include <cuda_runtime.h>

// HarmonicPolynomialR3Generator: out[i, :] = concat(1, f1, f2, ..., f10)
//   f1 = cob_1 @ p          (3)
//   fl = cob_l @ vec(f_{l-1} (x) f1)   (2l+1), l = 2..10
// Strategy: 2 points per thread packed in f32x2 lanes; cob matrices duplicated
// as 64-bit pairs in shared so each broadcast operand is one LDS.64 feeding one
// fma.rn.f32x2 (2 FMAs/lane-pair per instruction).

typedef unsigned long long ull;

__device__ __forceinline__ ull ffma2(ull a, ull b, ull c) {
    ull d;
    asm("fma.rn.f32x2 %0, %1, %2, %3;" : "=l"(d) : "l"(a), "l"(b), "l"(c));
    return d;
}
__device__ __forceinline__ ull fmul2(ull a, ull b) {
    ull d;
    asm("mul.rn.f32x2 %0, %1, %2;" : "=l"(d) : "l"(a), "l"(b));
    return d;
}
__device__ __forceinline__ ull pack2(float lo, float hi) {
    ull d;
    asm("mov.b64 %0, {%1, %2};" : "=l"(d) : "f"(lo), "f"(hi));
    return d;
}
__device__ __forceinline__ void st2(float* o0, float* o1, ull v) {
    float lo, hi;
    asm("mov.b64 {%0, %1}, %2;" : "=f"(lo), "=f"(hi) : "l"(v));
    __stcs(o0, lo);
    __stcs(o1, hi);
}

// cob_l element counts and offsets into the packed shared table
// l=1: 9 ; l>=2: (2l+1)*3*(2l-1)
#define COB_TOTAL 4590

// One recursion stage. PL = length of prev = 2l-1 ; output length PL+2 = 2l+1.
// cb points at this cob's first duplicated pair; cob is row-major [PL+2, 3*PL].
template <int PL>
__device__ __forceinline__ void stage(const ull* __restrict__ cb,
                                      const ull f1x, const ull f1y, const ull f1z,
                                      const ull* __restrict__ prev, ull* __restrict__ fout,
                                      float* __restrict__ o0, float* __restrict__ o1) {
#pragma unroll
    for (int k = 0; k < PL + 2; ++k) {
        const ull* row = cb + k * 3 * PL;
        // f[k] = sum_i sum_j cob[k, 3i+j] * prev[i] * f1[j]
        //      = f1x*a0 + f1y*a1 + f1z*a2, a_j = sum_i cob[k,3i+j]*prev[i]
        ull a0 = fmul2(row[0], prev[0]);
        ull a1 = fmul2(row[1], prev[0]);
        ull a2 = fmul2(row[2], prev[0]);
#pragma unroll
        for (int i = 1; i < PL; ++i) {
            a0 = ffma2(row[3 * i + 0], prev[i], a0);
            a1 = ffma2(row[3 * i + 1], prev[i], a1);
            a2 = ffma2(row[3 * i + 2], prev[i], a2);
        }
        ull r = ffma2(a0, f1x, ffma2(a1, f1y, fmul2(a2, f1z)));
        fout[k] = r;
        st2(o0 + k, o1 + k, r);
    }
}

__global__ void __launch_bounds__(256)
harmonic_kernel(const float* __restrict__ points,
                const float* __restrict__ c1, const float* __restrict__ c2,
                const float* __restrict__ c3, const float* __restrict__ c4,
                const float* __restrict__ c5, const float* __restrict__ c6,
                const float* __restrict__ c7, const float* __restrict__ c8,
                const float* __restrict__ c9, const float* __restrict__ c10,
                float* __restrict__ out, int N) {
    __shared__ ull scob[COB_TOTAL];  // each cob value duplicated in both f32 halves

    const int csz[10]  = {9, 45, 105, 189, 297, 429, 585, 765, 969, 1197};
    const int coff[10] = {0, 9, 54, 159, 348, 645, 1074, 1659, 2424, 3393};
    const float* cs[10] = {c1, c2, c3, c4, c5, c6, c7, c8, c9, c10};

#pragma unroll 1
    for (int a = 0; a < 10; ++a) {
        const float* c = cs[a];
        for (int e = threadIdx.x; e < csz[a]; e += blockDim.x) {
            float v = c[e];
            scob[coff[a] + e] = pack2(v, v);
        }
    }
    __syncthreads();

    const int t = blockIdx.x * blockDim.x + threadIdx.x;
    const int idx0 = 2 * t;
    if (idx0 >= N) return;  // N is even: idx0 < N implies idx1 < N

    // Load two points: floats [6t..6t+5] = p0x p0y p0z p1x p1y p1z
    const float2* p2 = reinterpret_cast<const float2*>(points);
    float2 q0 = p2[3 * t + 0];
    float2 q1 = p2[3 * t + 1];
    float2 q2 = p2[3 * t + 2];
    ull px = pack2(q0.x, q1.y);
    ull py = pack2(q0.y, q2.x);
    ull pz = pack2(q1.x, q2.y);

    // f1_j = sum_i cob1[j,i] * p_i
    ull f1x = ffma2(scob[0], px, ffma2(scob[1], py, fmul2(scob[2], pz)));
    ull f1y = ffma2(scob[3], px, ffma2(scob[4], py, fmul2(scob[5], pz)));
    ull f1z = ffma2(scob[6], px, ffma2(scob[7], py, fmul2(scob[8], pz)));

    float* o0 = out + (size_t)idx0 * 121;
    float* o1 = o0 + 121;

    __stcs(o0, 1.0f);
    __stcs(o1, 1.0f);
    st2(o0 + 1, o1 + 1, f1x);
    st2(o0 + 2, o1 + 2, f1y);
    st2(o0 + 3, o1 + 3, f1z);

    ull A[21], B[21];
    A[0] = f1x; A[1] = f1y; A[2] = f1z;

    // f_l lives at output offset l*l, length 2l+1
    stage<3>(scob + 9,    f1x, f1y, f1z, A, B, o0 + 4,   o1 + 4);    // l=2
    stage<5>(scob + 54,   f1x, f1y, f1z, B, A, o0 + 9,   o1 + 9);    // l=3
    stage<7>(scob + 159,  f1x, f1y, f1z, A, B, o0 + 16,  o1 + 16);   // l=4
    stage<9>(scob + 348,  f1x, f1y, f1z, B, A, o0 + 25,  o1 + 25);   // l=5
    stage<11>(scob + 645, f1x, f1y, f1z, A, B, o0 + 36,  o1 + 36);   // l=6
    stage<13>(scob + 1074,f1x, f1y, f1z, B, A, o0 + 49,  o1 + 49);   // l=7
    stage<15>(scob + 1659,f1x, f1y, f1z, A, B, o0 + 64,  o1 + 64);   // l=8
    stage<17>(scob + 2424,f1x, f1y, f1z, B, A, o0 + 81,  o1 + 81);   // l=9
    stage<19>(scob + 3393,f1x, f1y, f1z, A, B, o0 + 100, o1 + 100);  // l=10
}

extern "C" void kernel_launch(void* const* d_in, const int* in_sizes, int n_in,
                              void* d_out, int out_size) {
    const float* points = (const float*)d_in[0];
    const int N = in_sizes[0] / 3;
    float* out = (float*)d_out;

    const int nhalf = (N + 1) / 2;
    const int block = 256;
    const int grid = (nhalf + block - 1) / block;

    harmonic_kernel<<<grid, block>>>(
        points,
        (const float*)d_in[1], (const float*)d_in[2], (const float*)d_in[3],
        (const float*)d_in[4], (const float*)d_in[5], (const float*)d_in[6],
        (const float*)d_in[7], (const float*)d_in[8], (const float*)d_in[9],
        (const float*)d_in[10],
        out, N);
}

// round 2
// speedup vs baseline: 1.3198x; 1.3198x over previous
#include <cuda_runtime.h>
#include <cstdint>

// HarmonicPolynomialR3Generator
// out[i,:] = concat(1, f1, f2..f10), f1 = cob1 @ p, fl = cob_l @ vec(f_{l-1} ⊗ f1).
//
// R2 strategy:
//  - 2 points per thread in fma.rn.f32x2 lanes (points tid and tid+64 of the tile)
//  - cob matrices in smem, duplicated as (v,v) 64-bit pairs, COLUMN-major with
//    even stride so operand fetches are aligned broadcast LDS.128 (2 ops/load)
//  - outputs staged in a smem tile buffer [128 points][121 floats] (STS lane
//    stride 121 floats = odd -> conflict-free), then ONE cp.async.bulk
//    shared->global per CTA (tile rows are contiguous in gmem). Kills the
//    scattered-STG wavefront bottleneck from R1.
//  - 101KB smem/CTA, 64 threads, 2 CTAs/SM so TMA-wait overlaps compute.

typedef unsigned long long ull;

__device__ __forceinline__ ull ffma2(ull a, ull b, ull c) {
    ull d; asm("fma.rn.f32x2 %0, %1, %2, %3;" : "=l"(d) : "l"(a), "l"(b), "l"(c)); return d;
}
__device__ __forceinline__ ull fmul2(ull a, ull b) {
    ull d; asm("mul.rn.f32x2 %0, %1, %2;" : "=l"(d) : "l"(a), "l"(b)); return d;
}
__device__ __forceinline__ ull pack2(float lo, float hi) {
    ull d; asm("mov.b64 %0, {%1, %2};" : "=l"(d) : "f"(lo), "f"(hi)); return d;
}
__device__ __forceinline__ void st2s(float* a, float* b, ull v) {
    float lo, hi; asm("mov.b64 {%0, %1}, %2;" : "=f"(lo), "=f"(hi) : "l"(v));
    *a = lo; *b = hi;
}
__device__ __forceinline__ uint32_t smem_u32(const void* p) {
    uint32_t a;
    asm("{ .reg .u64 t; cvta.to.shared.u64 t, %1; cvt.u32.u64 %0, t; }" : "=r"(a) : "l"(p));
    return a;
}

// cob smem offsets (in ull units). l=1 row-major 9 (pad to 10); l>=2 column-major
// [3*PL][S] with PL=2l-1, S=PL+3 (even stride -> 16B-aligned columns).
#define OFF2   10
#define OFF3   64
#define OFF4   184
#define OFF5   394
#define OFF6   718
#define OFF7   1180
#define OFF8   1804
#define OFF9   2614
#define OFF10  3634
#define COB_ULL 4888

#define TILE_PTS 128
#define BLOCK    64
#define BUF_FLOATS (TILE_PTS * 121)
#define SMEM_BYTES (COB_ULL * 8 + BUF_FLOATS * 4)   // 39104 + 61952 = 101056

// Load cob_l (global row-major [PL+2][3PL]) into smem column-major duplicated pairs.
template <int PL>
__device__ __forceinline__ void load_cob(const float* __restrict__ c, ull* __restrict__ dst, int tid) {
    constexpr int M = 3 * PL;
    constexpr int NK = PL + 2;
    constexpr int S = PL + 3;
    for (int e = tid; e < NK * M; e += BLOCK) {
        int k = e / M;
        int m = e - k * M;
        float v = c[e];
        dst[m * S + k] = pack2(v, v);
    }
}

// One recursion stage. prev has PL entries; produces NK = PL+2 outputs.
// cb: column-major [3PL][S] duplicated pairs. b0/b1 point at this stage's
// output offset (l*l) within the two smem buffer rows.
template <int PL>
__device__ __forceinline__ void stage(const ull* __restrict__ cb,
                                      const ull f1x, const ull f1y, const ull f1z,
                                      const ull* __restrict__ prev, ull* __restrict__ fout,
                                      float* __restrict__ b0, float* __restrict__ b1) {
    constexpr int NK = PL + 2;   // odd
    constexpr int S  = PL + 3;   // even
    ull acc[NK];
    {
        ull g = fmul2(prev[0], f1x);   // m = 0: i=0, j=0
#pragma unroll
        for (int k = 0; k + 1 < NK; k += 2) {
            ulonglong2 v = *reinterpret_cast<const ulonglong2*>(cb + k);
            acc[k]     = fmul2(v.x, g);
            acc[k + 1] = fmul2(v.y, g);
        }
        acc[NK - 1] = fmul2(cb[NK - 1], g);
    }
#pragma unroll
    for (int m = 1; m < 3 * PL; ++m) {
        const int i = m / 3, j = m % 3;
        ull fj = (j == 0) ? f1x : (j == 1) ? f1y : f1z;
        ull g = fmul2(prev[i], fj);
        const ull* col = cb + m * S;
#pragma unroll
        for (int k = 0; k + 1 < NK; k += 2) {
            ulonglong2 v = *reinterpret_cast<const ulonglong2*>(col + k);
            acc[k]     = ffma2(v.x, g, acc[k]);
            acc[k + 1] = ffma2(v.y, g, acc[k + 1]);
        }
        acc[NK - 1] = ffma2(col[NK - 1], g, acc[NK - 1]);
    }
#pragma unroll
    for (int k = 0; k < NK; ++k) {
        fout[k] = acc[k];
        st2s(b0 + k, b1 + k, acc[k]);
    }
}

__global__ void __launch_bounds__(BLOCK, 2)
harmonic_kernel(const float* __restrict__ pts,
                const float* __restrict__ c1, const float* __restrict__ c2,
                const float* __restrict__ c3, const float* __restrict__ c4,
                const float* __restrict__ c5, const float* __restrict__ c6,
                const float* __restrict__ c7, const float* __restrict__ c8,
                const float* __restrict__ c9, const float* __restrict__ c10,
                float* __restrict__ out, int N) {
    extern __shared__ ull dyns[];
    ull* scob = dyns;
    float* buf = reinterpret_cast<float*>(dyns + COB_ULL);
    const int tid = threadIdx.x;

    // ---- load cob tables ----
    if (tid < 9) { float v = c1[tid]; scob[tid] = pack2(v, v); }
    load_cob<3>(c2, scob + OFF2, tid);
    load_cob<5>(c3, scob + OFF3, tid);
    load_cob<7>(c4, scob + OFF4, tid);
    load_cob<9>(c5, scob + OFF5, tid);
    load_cob<11>(c6, scob + OFF6, tid);
    load_cob<13>(c7, scob + OFF7, tid);
    load_cob<15>(c8, scob + OFF8, tid);
    load_cob<17>(c9, scob + OFF9, tid);
    load_cob<19>(c10, scob + OFF10, tid);
    __syncthreads();

    const int base = blockIdx.x * TILE_PTS;
    int rem = N - base; if (rem > TILE_PTS) rem = TILE_PTS;
    const int lo = base + tid;
    const int hi = base + BLOCK + tid;

    float ax = 0.f, ay = 0.f, az = 0.f, bx = 0.f, by = 0.f, bz = 0.f;
    if (lo < N) { ax = pts[3 * lo]; ay = pts[3 * lo + 1]; az = pts[3 * lo + 2]; }
    if (hi < N) { bx = pts[3 * hi]; by = pts[3 * hi + 1]; bz = pts[3 * hi + 2]; }
    ull px = pack2(ax, bx), py = pack2(ay, by), pz = pack2(az, bz);

    // f1_j = sum_i cob1[j,i] * p_i
    ull f1x = ffma2(scob[0], px, ffma2(scob[1], py, fmul2(scob[2], pz)));
    ull f1y = ffma2(scob[3], px, ffma2(scob[4], py, fmul2(scob[5], pz)));
    ull f1z = ffma2(scob[6], px, ffma2(scob[7], py, fmul2(scob[8], pz)));

    float* b0 = buf + tid * 121;
    float* b1 = buf + (tid + BLOCK) * 121;
    b0[0] = 1.0f; b1[0] = 1.0f;
    st2s(b0 + 1, b1 + 1, f1x);
    st2s(b0 + 2, b1 + 2, f1y);
    st2s(b0 + 3, b1 + 3, f1z);

    ull A[21], B[21];
    A[0] = f1x; A[1] = f1y; A[2] = f1z;

    stage<3>(scob + OFF2,  f1x, f1y, f1z, A, B, b0 + 4,   b1 + 4);    // l=2
    stage<5>(scob + OFF3,  f1x, f1y, f1z, B, A, b0 + 9,   b1 + 9);    // l=3
    stage<7>(scob + OFF4,  f1x, f1y, f1z, A, B, b0 + 16,  b1 + 16);   // l=4
    stage<9>(scob + OFF5,  f1x, f1y, f1z, B, A, b0 + 25,  b1 + 25);   // l=5
    stage<11>(scob + OFF6, f1x, f1y, f1z, A, B, b0 + 36,  b1 + 36);   // l=6
    stage<13>(scob + OFF7, f1x, f1y, f1z, B, A, b0 + 49,  b1 + 49);   // l=7
    stage<15>(scob + OFF8, f1x, f1y, f1z, A, B, b0 + 64,  b1 + 64);   // l=8
    stage<17>(scob + OFF9, f1x, f1y, f1z, B, A, b0 + 81,  b1 + 81);   // l=9
    stage<19>(scob + OFF10,f1x, f1y, f1z, A, B, b0 + 100, b1 + 100);  // l=10

    __syncthreads();
    asm volatile("fence.proxy.async.shared::cta;" ::: "memory");

    // One bulk async store: tile rows are contiguous in gmem.
    const unsigned bytes = (unsigned)rem * 121u * 4u;
    const unsigned mainb = bytes & ~15u;
    float* gdst = out + (size_t)base * 121;
    if (tid == 0 && mainb) {
        uint32_t saddr = smem_u32(buf);
        asm volatile("cp.async.bulk.global.shared::cta.bulk_group [%0], [%1], %2;"
                     :: "l"(gdst), "r"(saddr), "r"(mainb) : "memory");
        asm volatile("cp.async.bulk.commit_group;" ::: "memory");
    }
    // scalar tail (only if rem*121*4 not a multiple of 16; never for full tiles)
    for (int e = (int)(mainb >> 2) + tid; e < rem * 121; e += BLOCK)
        gdst[e] = buf[e];
    if (tid == 0 && mainb)
        asm volatile("cp.async.bulk.wait_group 0;" ::: "memory");
}

extern "C" void kernel_launch(void* const* d_in, const int* in_sizes, int n_in,
                              void* d_out, int out_size) {
    const float* points = (const float*)d_in[0];
    const int N = in_sizes[0] / 3;
    float* out = (float*)d_out;

    cudaFuncSetAttribute(harmonic_kernel,
                         cudaFuncAttributeMaxDynamicSharedMemorySize, SMEM_BYTES);

    const int grid = (N + TILE_PTS - 1) / TILE_PTS;
    harmonic_kernel<<<grid, BLOCK, SMEM_BYTES>>>(
        points,
        (const float*)d_in[1], (const float*)d_in[2], (const float*)d_in[3],
        (const float*)d_in[4], (const float*)d_in[5], (const float*)d_in[6],
        (const float*)d_in[7], (const float*)d_in[8], (const float*)d_in[9],
        (const float*)d_in[10],
        out, N);
}